// round 6
// baseline (speedup 1.0000x reference)
#include <cuda_runtime.h>
#include <cstdint>

// BinaryConv2d: x (8,16,1024,1024) f32, weight (16,16,3,3) in {0,1} -> +/-1
// stride (2,2), pad (1,1) -> out (8,16,512,512)
//
// R6: NO smem staging for x. Input read directly via predicated LDG
// (L1-cached; tile/SM ~34KB << 228KB L1). Signs in shared (broadcast
// LDS.128). FFMA2 (f32x2) oc-pair-packed accumulators, 4 px/thread.

#define N_BATCH 8
#define C_IN    16
#define C_OUT   16
#define IN_HW   1024
#define OUT_HW  512

#define TH 16              // output rows per block (4 per warp)
#define TW 32              // output cols per block
#define NTHREADS 128

__device__ __forceinline__ unsigned long long bcast2(float x) {
    unsigned long long r;
    asm("mov.b64 %0, {%1, %1};" : "=l"(r) : "f"(x));
    return r;
}

__device__ __forceinline__ void ffma2(unsigned long long& acc,
                                      unsigned long long a,
                                      unsigned long long b) {
    asm("fma.rn.f32x2 %0, %1, %2, %0;" : "+l"(acc) : "l"(a), "l"(b));
}

__device__ __forceinline__ float2 unpack2(unsigned long long v) {
    float2 f;
    asm("mov.b64 {%0, %1}, %2;" : "=f"(f.x), "=f"(f.y) : "l"(v));
    return f;
}

__global__ void __launch_bounds__(NTHREADS, 4)
binconv_kernel(const float* __restrict__ x,
               const float* __restrict__ w,
               float* __restrict__ out) {
    __shared__ __align__(16) float s_sgn[C_IN * 9 * C_OUT];   // [c][tap][oc]

    const int tid  = threadIdx.x;
    const int wrp  = tid >> 5;
    const int lane = tid & 31;
    const int tx   = lane & 7;          // x-group (4 output px)
    const int ty   = (lane >> 3) & 3;   // output row within warp band

    const int n  = blockIdx.z;
    const int y0 = blockIdx.y * TH;
    const int x0 = blockIdx.x * TW;

    // ---- decode weights into shared sign table (oc fastest) ----
    #pragma unroll
    for (int idx = tid; idx < C_OUT * C_IN * 9; idx += NTHREADS) {
        int oc  = idx / (C_IN * 9);
        int rem = idx - oc * (C_IN * 9);          // c*9 + tap
        s_sgn[rem * C_OUT + oc] = (w[idx] == 1.0f) ? 1.0f : -1.0f;
    }
    __syncthreads();

    // ---- per-thread input geometry (channel-invariant) ----
    const int oy  = y0 + 4 * wrp + ty;            // this thread's output row
    const int iy0 = 2 * oy - 1;                   // input row for tap r=0
    const int gxA = 2 * x0 + 8 * tx;              // aligned col of A.x  (x_{0})
    const bool eok = (gxA > 0);                   // left edge col valid?

    const float* xn = x + ((size_t)n << 24);
    // base pointer at (row iy0, col gxA); iy0 may be -1 (never dereferenced then)
    const float* pbase = xn + (ptrdiff_t)iy0 * IN_HW + gxA;

    bool rok[3];
    #pragma unroll
    for (int r = 0; r < 3; ++r)
        rok[r] = (iy0 + r) >= 0;                  // bottom rows always in-bounds

    // accumulators: [oc_pair 0..7][px 0..3] packed f32x2
    unsigned long long acc[8][4];
    #pragma unroll
    for (int i = 0; i < 8; ++i)
        #pragma unroll
        for (int p = 0; p < 4; ++p)
            acc[i][p] = 0ull;

    #pragma unroll 1
    for (int c = 0; c < C_IN; ++c) {
        const float* pc = pbase + ((size_t)c << 20);
        const float* sgn_c = s_sgn + c * 9 * C_OUT;

        // ---- load all 3 input rows (9 values each) up front: max MLP ----
        float  xm1[3];
        float4 A[3], B[3];
        #pragma unroll
        for (int r = 0; r < 3; ++r) {
            const float* rp = pc + r * IN_HW;
            A[r] = make_float4(0.f, 0.f, 0.f, 0.f);
            B[r] = make_float4(0.f, 0.f, 0.f, 0.f);
            xm1[r] = 0.f;
            if (rok[r]) {
                A[r] = *(const float4*)rp;        // cols 0..3 (16B aligned)
                B[r] = *(const float4*)(rp + 4);  // cols 4..7
                if (eok) xm1[r] = rp[-1];         // col -1
            }
        }

        #pragma unroll
        for (int r = 0; r < 3; ++r) {
            unsigned long long xv[9];
            xv[0] = bcast2(xm1[r]);
            xv[1] = bcast2(A[r].x); xv[2] = bcast2(A[r].y);
            xv[3] = bcast2(A[r].z); xv[4] = bcast2(A[r].w);
            xv[5] = bcast2(B[r].x); xv[6] = bcast2(B[r].y);
            xv[7] = bcast2(B[r].z); xv[8] = bcast2(B[r].w);

            #pragma unroll
            for (int j = 0; j < 3; ++j) {
                const ulonglong2* sp =
                    (const ulonglong2*)(sgn_c + (r * 3 + j) * C_OUT);
                ulonglong2 s0 = sp[0];   // broadcast LDS.128, conflict-free
                ulonglong2 s1 = sp[1];
                ulonglong2 s2 = sp[2];
                ulonglong2 s3 = sp[3];
                unsigned long long sv[8] =
                    { s0.x, s0.y, s1.x, s1.y, s2.x, s2.y, s3.x, s3.y };

                #pragma unroll
                for (int p = 0; p < 4; ++p) {
                    unsigned long long xvp = xv[2 * p + j];
                    #pragma unroll
                    for (int i = 0; i < 8; ++i)
                        ffma2(acc[i][p], xvp, sv[i]);
                }
            }
        }
    }

    // ---- writeout: 16 oc x 4 consecutive x -> float4 per oc ----
    const int ox = x0 + 4 * tx;
    float* ob = out + (((size_t)n * C_OUT) * OUT_HW + oy) * OUT_HW + ox;

    #pragma unroll
    for (int i = 0; i < 8; ++i) {
        float2 f0 = unpack2(acc[i][0]);
        float2 f1 = unpack2(acc[i][1]);
        float2 f2 = unpack2(acc[i][2]);
        float2 f3 = unpack2(acc[i][3]);
        float4 lo = make_float4(f0.x, f1.x, f2.x, f3.x);
        float4 hi = make_float4(f0.y, f1.y, f2.y, f3.y);
        *(float4*)(ob + (size_t)(2 * i)     * OUT_HW * OUT_HW) = lo;
        *(float4*)(ob + (size_t)(2 * i + 1) * OUT_HW * OUT_HW) = hi;
    }
}

extern "C" void kernel_launch(void* const* d_in, const int* in_sizes, int n_in,
                              void* d_out, int out_size) {
    const float* x = (const float*)d_in[0];
    const float* w = (const float*)d_in[1];
    float* out = (float*)d_out;

    dim3 grid(OUT_HW / TW, OUT_HW / TH, N_BATCH);   // (16, 32, 8)
    dim3 block(NTHREADS);
    binconv_kernel<<<grid, block>>>(x, w, out);
}

// round 7
// speedup vs baseline: 1.0587x; 1.0587x over previous
#include <cuda_runtime.h>
#include <cstdint>

// BinaryConv2d: x (8,16,1024,1024) f32, weight (16,16,3,3) in {0,1} -> +/-1
// stride (2,2), pad (1,1) -> out (8,16,512,512)
//
// R7 = R6 (direct predicated LDG, no x staging) +
//   * prefetch.global.L1 of next channel's rows (register-free lookahead)
//   * edge column via __shfl_up (neighbor lane's B.w), LDG only for tx==0

#define N_BATCH 8
#define C_IN    16
#define C_OUT   16
#define IN_HW   1024
#define OUT_HW  512

#define TH 16              // output rows per block (4 per warp)
#define TW 32              // output cols per block
#define NTHREADS 128

__device__ __forceinline__ unsigned long long bcast2(float x) {
    unsigned long long r;
    asm("mov.b64 %0, {%1, %1};" : "=l"(r) : "f"(x));
    return r;
}

__device__ __forceinline__ void ffma2(unsigned long long& acc,
                                      unsigned long long a,
                                      unsigned long long b) {
    asm("fma.rn.f32x2 %0, %1, %2, %0;" : "+l"(acc) : "l"(a), "l"(b));
}

__device__ __forceinline__ float2 unpack2(unsigned long long v) {
    float2 f;
    asm("mov.b64 {%0, %1}, %2;" : "=f"(f.x), "=f"(f.y) : "l"(v));
    return f;
}

__device__ __forceinline__ void prefetch_l1(const float* p) {
    asm volatile("prefetch.global.L1 [%0];" :: "l"(p));
}

__global__ void __launch_bounds__(NTHREADS, 4)
binconv_kernel(const float* __restrict__ x,
               const float* __restrict__ w,
               float* __restrict__ out) {
    __shared__ __align__(16) float s_sgn[C_IN * 9 * C_OUT];   // [c][tap][oc]

    const int tid  = threadIdx.x;
    const int wrp  = tid >> 5;
    const int lane = tid & 31;
    const int tx   = lane & 7;          // x-group (4 output px)
    const int ty   = (lane >> 3) & 3;   // output row within warp band

    const int n  = blockIdx.z;
    const int y0 = blockIdx.y * TH;
    const int x0 = blockIdx.x * TW;

    // ---- decode weights into shared sign table (oc fastest) ----
    #pragma unroll
    for (int idx = tid; idx < C_OUT * C_IN * 9; idx += NTHREADS) {
        int oc  = idx / (C_IN * 9);
        int rem = idx - oc * (C_IN * 9);          // c*9 + tap
        s_sgn[rem * C_OUT + oc] = (w[idx] == 1.0f) ? 1.0f : -1.0f;
    }
    __syncthreads();

    // ---- per-thread input geometry (channel-invariant) ----
    const int oy  = y0 + 4 * wrp + ty;            // this thread's output row
    const int iy0 = 2 * oy - 1;                   // input row for tap r=0
    const int gxA = 2 * x0 + 8 * tx;              // aligned col of A.x
    const bool eldg = (tx == 0) && (gxA > 0);     // tx==0 needs LDG for col-1

    const float* xn = x + ((size_t)n << 24);
    const float* pbase = xn + (ptrdiff_t)iy0 * IN_HW + gxA;

    bool rok[3];
    #pragma unroll
    for (int r = 0; r < 3; ++r)
        rok[r] = (iy0 + r) >= 0;                  // only top row can be OOB

    // accumulators: [oc_pair 0..7][px 0..3] packed f32x2
    unsigned long long acc[8][4];
    #pragma unroll
    for (int i = 0; i < 8; ++i)
        #pragma unroll
        for (int p = 0; p < 4; ++p)
            acc[i][p] = 0ull;

    // warm L1 for channel 0
    #pragma unroll
    for (int r = 0; r < 3; ++r)
        if (rok[r]) prefetch_l1(pbase + r * IN_HW);

    #pragma unroll 1
    for (int c = 0; c < C_IN; ++c) {
        const float* pc = pbase + ((size_t)c << 20);
        const float* sgn_c = s_sgn + c * 9 * C_OUT;

        // ---- load 3 rows (A,B) + tx==0 edge; then prefetch next channel ----
        float  e[3];
        float4 A[3], B[3];
        #pragma unroll
        for (int r = 0; r < 3; ++r) {
            const float* rp = pc + r * IN_HW;
            A[r] = make_float4(0.f, 0.f, 0.f, 0.f);
            B[r] = make_float4(0.f, 0.f, 0.f, 0.f);
            e[r] = 0.f;
            if (rok[r]) {
                A[r] = *(const float4*)rp;        // cols 0..3 (16B aligned)
                B[r] = *(const float4*)(rp + 4);  // cols 4..7
            }
            if (eldg && rok[r]) e[r] = rp[-1];    // 4 lanes only
        }

        if (c + 1 < C_IN) {
            const float* pn = pc + (1 << 20);
            #pragma unroll
            for (int r = 0; r < 3; ++r)
                if (rok[r]) prefetch_l1(pn + r * IN_HW);
        }

        // edge x_{-1} for tx>0 comes from neighbor lane's B.w
        float xm1[3];
        #pragma unroll
        for (int r = 0; r < 3; ++r) {
            float nb = __shfl_up_sync(0xffffffffu, B[r].w, 1);
            xm1[r] = (tx == 0) ? e[r] : nb;
        }

        #pragma unroll
        for (int r = 0; r < 3; ++r) {
            unsigned long long xv[9];
            xv[0] = bcast2(xm1[r]);
            xv[1] = bcast2(A[r].x); xv[2] = bcast2(A[r].y);
            xv[3] = bcast2(A[r].z); xv[4] = bcast2(A[r].w);
            xv[5] = bcast2(B[r].x); xv[6] = bcast2(B[r].y);
            xv[7] = bcast2(B[r].z); xv[8] = bcast2(B[r].w);

            #pragma unroll
            for (int j = 0; j < 3; ++j) {
                const ulonglong2* sp =
                    (const ulonglong2*)(sgn_c + (r * 3 + j) * C_OUT);
                ulonglong2 s0 = sp[0];   // broadcast LDS.128, conflict-free
                ulonglong2 s1 = sp[1];
                ulonglong2 s2 = sp[2];
                ulonglong2 s3 = sp[3];
                unsigned long long sv[8] =
                    { s0.x, s0.y, s1.x, s1.y, s2.x, s2.y, s3.x, s3.y };

                #pragma unroll
                for (int p = 0; p < 4; ++p) {
                    unsigned long long xvp = xv[2 * p + j];
                    #pragma unroll
                    for (int i = 0; i < 8; ++i)
                        ffma2(acc[i][p], xvp, sv[i]);
                }
            }
        }
    }

    // ---- writeout: 16 oc x 4 consecutive x -> float4 per oc ----
    const int ox = x0 + 4 * tx;
    float* ob = out + (((size_t)n * C_OUT) * OUT_HW + oy) * OUT_HW + ox;

    #pragma unroll
    for (int i = 0; i < 8; ++i) {
        float2 f0 = unpack2(acc[i][0]);
        float2 f1 = unpack2(acc[i][1]);
        float2 f2 = unpack2(acc[i][2]);
        float2 f3 = unpack2(acc[i][3]);
        float4 lo = make_float4(f0.x, f1.x, f2.x, f3.x);
        float4 hi = make_float4(f0.y, f1.y, f2.y, f3.y);
        *(float4*)(ob + (size_t)(2 * i)     * OUT_HW * OUT_HW) = lo;
        *(float4*)(ob + (size_t)(2 * i + 1) * OUT_HW * OUT_HW) = hi;
    }
}

extern "C" void kernel_launch(void* const* d_in, const int* in_sizes, int n_in,
                              void* d_out, int out_size) {
    const float* x = (const float*)d_in[0];
    const float* w = (const float*)d_in[1];
    float* out = (float*)d_out;

    dim3 grid(OUT_HW / TW, OUT_HW / TH, N_BATCH);   // (16, 32, 8)
    dim3 block(NTHREADS);
    binconv_kernel<<<grid, block>>>(x, w, out);
}